// round 15
// baseline (speedup 1.0000x reference)
#include <cuda_runtime.h>
#include <cstdint>
#include <cstdio>

#define NTOK  131072
#define DIM   128
#define NCODE 1024
#define NLVL  4

#define BM    64                 // tokens per CTA
#define ARGMIN_GRID (NTOK / BM)  // 2048
#define RES_GRID    (NTOK * (DIM / 4) / 256)     // 16384
#define FINAL_ROWS  16
#define FINAL_GRID  (NTOK / FINAL_ROWS)          // 8192
#define PREP_GRID   (NLVL * NCODE / 8)           // 512

#define MARGIN 2e-4f             // capture margin in s-domain

#define LSTRIDE 260              // Aperm per-lane stride (words): 260 % 32 == 4

// ---- small float-only device global (validated safe in R12) ----
__device__ float g_en2[NLVL * NCODE];   // 16 KB

// ---- legacy tensor-core mma (sm_80+; compiles on sm_100 base) ----
#define MMA_TF32(d, a, b0, b1)                                              \
    asm volatile("mma.sync.aligned.m16n8k8.row.col.f32.tf32.tf32.f32 "      \
        "{%0,%1,%2,%3}, {%4,%5,%6,%7}, {%8,%9}, {%0,%1,%2,%3};"             \
        : "+f"((d)[0]), "+f"((d)[1]), "+f"((d)[2]), "+f"((d)[3])            \
        : "r"((a)[0]), "r"((a)[1]), "r"((a)[2]), "r"((a)[3]),               \
          "r"(b0), "r"(b1))

__device__ __forceinline__ uint32_t tf32_of(float x)
{
    uint32_t h;
    asm("cvt.rna.tf32.f32 %0, %1;" : "=r"(h) : "f"(x));
    return h;
}

__device__ __forceinline__ unsigned long long umin64(unsigned long long a,
                                                     unsigned long long b)
{ return a < b ? a : b; }
__device__ __forceinline__ unsigned long long umax64(unsigned long long a,
                                                     unsigned long long b)
{ return a > b ? a : b; }

// ---------------------------------------------------------------------------
// prep: en2[r] = sum_d e[r][d]^2 for ALL levels (bit-identical R7 formula).
// ---------------------------------------------------------------------------
__global__ void __launch_bounds__(256)
prep_kernel(const float* __restrict__ embedding, int early)
{
    if (early) return;
    int lane = threadIdx.x & 31;
    int row  = blockIdx.x * 8 + (threadIdx.x >> 5);   // 0..4095
    float4 v = reinterpret_cast<const float4*>(embedding + (size_t)row * DIM)[lane];
    float p = __fadd_rn(__fadd_rn(__fadd_rn(__fmul_rn(v.x, v.x),
                                            __fmul_rn(v.y, v.y)),
                                  __fmul_rn(v.z, v.z)),
                        __fmul_rn(v.w, v.w));
    #pragma unroll
    for (int off = 16; off >= 1; off >>= 1)
        p = __fadd_rn(p, __shfl_down_sync(0xffffffffu, p, off));
    if (lane == 0) g_en2[row] = p;
}

// exact R7-bit-identical rescore: sequential-d fp32 fmaf dot + binned dist;
// lowest-index tie-break via packed u64 atomicMin (exact dist domain).
__device__ __forceinline__ void rescore(const float4* __restrict__ srow4,
                                        const float* __restrict__ embed,
                                        const float* en2s, const float* rn2s,
                                        unsigned long long* cand,
                                        int row, int k)
{
    const float4* e4 = reinterpret_cast<const float4*>(embed + (size_t)k * DIM);
    float dot = 0.f;
    #pragma unroll 8
    for (int i = 0; i < 32; i++) {
        float4 a = __ldg(srow4 + i);
        float4 e = __ldg(e4 + i);
        dot = fmaf(a.x, e.x, dot);
        dot = fmaf(a.y, e.y, dot);
        dot = fmaf(a.z, e.z, dot);
        dot = fmaf(a.w, e.w, dot);
    }
    float dist = __fsub_rn(__fadd_rn(rn2s[row], en2s[k]), __fmul_rn(2.0f, dot));
    unsigned long long p =
        ((unsigned long long)__float_as_uint(dist) << 32) | (unsigned)k;
    atomicMin(cand + row, p);
}

// ---------------------------------------------------------------------------
// argmin (R13 structure): 8 warps x 128 codes, Aperm smem LDS.128 A-frags,
// bias folded into GEMM, B software-pipelined one step ahead in registers.
// ---------------------------------------------------------------------------
__global__ void __launch_bounds__(256)
argmin_kernel(const float* __restrict__ src,     // N x D (inputs or residual)
              const float* __restrict__ embed,   // K x D, this level (fp32)
              const float* __restrict__ en2g,    // K, this level (from g_en2)
              float* __restrict__ idx_out,       // N floats, this level slice
              int early)
{
    if (early) return;

    __shared__ uint32_t Aperm[32 * LSTRIDE];     // 33.3 KB fragment-major tf32
    __shared__ float en2s[NCODE];                // 4 KB
    __shared__ float rn2s[BM];
    __shared__ unsigned long long redp[8][BM];   // per-warp packed approx min
    __shared__ float minv[BM];
    __shared__ unsigned long long cand[BM];

    const int tid  = threadIdx.x;
    const int wid  = tid >> 5, lane = tid & 31;
    const int m0blk = blockIdx.x * BM;
    const float4* __restrict__ src4 =
        reinterpret_cast<const float4*>(src) + (size_t)m0blk * (DIM / 4);

    // ---- en2 slice: global -> smem (coalesced float4) ----
    {
        const float4* g4 = reinterpret_cast<const float4*>(en2g);
        float4* s4 = reinterpret_cast<float4*>(en2s);
        for (int j = tid; j < NCODE / 4; j += 256) s4[j] = __ldg(g4 + j);
    }

    // ---- A panel -> Aperm (tf32 RN-rounded, mma-fragment-major layout) ----
    #pragma unroll
    for (int i = 0; i < 8; i++) {
        int flat = tid + i * 256;
        int row = flat >> 5, c4 = flat & 31;
        float4 v = src4[(size_t)row * (DIM / 4) + c4];
        int ks = c4 >> 1, colhalf = c4 & 1;
        int r_l = row & 7, rowhalf = (row >> 3) & 1, mt = row >> 4;
        int q = rowhalf + 2 * colhalf;
        int base = (r_l * 4) * LSTRIDE + mt * 64 + ks * 4 + q;
        Aperm[base + 0 * LSTRIDE] = tf32_of(v.x);
        Aperm[base + 1 * LSTRIDE] = tf32_of(v.y);
        Aperm[base + 2 * LSTRIDE] = tf32_of(v.z);
        Aperm[base + 3 * LSTRIDE] = tf32_of(v.w);
    }

    // ---- rn2 from EXACT global values: bit-identical to R7 ----
    for (int r = wid; r < BM; r += 8) {
        float4 v = src4[(size_t)r * (DIM / 4) + lane];
        float p = __fadd_rn(__fadd_rn(__fadd_rn(__fmul_rn(v.x, v.x),
                                                __fmul_rn(v.y, v.y)),
                                      __fmul_rn(v.z, v.z)),
                            __fmul_rn(v.w, v.w));
        #pragma unroll
        for (int off = 16; off >= 1; off >>= 1)
            p = __fadd_rn(p, __shfl_down_sync(0xffffffffu, p, off));
        if (lane == 0) rn2s[r] = p;
    }
    __syncthreads();

    const int r_lane = lane >> 2;   // 0..7
    const int c_lane = lane & 3;    // 0..3
    const int n_warp0 = wid * 128;  // this warp's 128-code range

    // extra-K A fragments (bias columns): a=1 for k=0,1
    uint32_t aHe[4];
    aHe[0] = aHe[1] = (c_lane <= 1) ? __float_as_uint(1.0f) : 0u;
    aHe[2] = aHe[3] = 0u;

    // per-thread packed top-2 in s-domain
    unsigned long long b1[4][2], b2[4][2];
    #pragma unroll
    for (int mt = 0; mt < 4; mt++)
        #pragma unroll
        for (int h = 0; h < 2; h++) { b1[mt][h] = ~0ull; b2[mt][h] = ~0ull; }

    // ---- B pipeline: preload (nblk=0, ks=0) ----
    uint32_t nb0[4], nb1[4];
    #pragma unroll
    for (int nt = 0; nt < 4; nt++) {
        const float* ep = embed + (size_t)(n_warp0 + nt * 8 + r_lane) * DIM + c_lane;
        nb0[nt] = __float_as_uint(__ldg(ep));
        nb1[nt] = __float_as_uint(__ldg(ep + 4));
    }

    for (int nblk = 0; nblk < 4; nblk++) {
        const int n0 = n_warp0 + nblk * 32;
        const bool lastblk = (nblk == 3);

        float acc[4][4][4];   // [nt][mt][frag]
        #pragma unroll
        for (int nt = 0; nt < 4; nt++)
            #pragma unroll
            for (int mt = 0; mt < 4; mt++)
                #pragma unroll
                for (int q = 0; q < 4; q++) acc[nt][mt][q] = 0.f;

        #pragma unroll
        for (int ks = 0; ks < 16; ks++) {
            // consume prefetched B, then prefetch next step
            uint32_t cb0[4], cb1[4];
            #pragma unroll
            for (int nt = 0; nt < 4; nt++) { cb0[nt] = nb0[nt]; cb1[nt] = nb1[nt]; }

            if (ks < 15) {
                const int nk0 = (ks + 1) * 8;
                #pragma unroll
                for (int nt = 0; nt < 4; nt++) {
                    const float* ep = embed +
                        (size_t)(n0 + nt * 8 + r_lane) * DIM + nk0 + c_lane;
                    nb0[nt] = __float_as_uint(__ldg(ep));
                    nb1[nt] = __float_as_uint(__ldg(ep + 4));
                }
            } else if (!lastblk) {
                #pragma unroll
                for (int nt = 0; nt < 4; nt++) {
                    const float* ep = embed +
                        (size_t)(n0 + 32 + nt * 8 + r_lane) * DIM + c_lane;
                    nb0[nt] = __float_as_uint(__ldg(ep));
                    nb1[nt] = __float_as_uint(__ldg(ep + 4));
                }
            }

            // A fragments: one LDS.128 per mt (broadcast across warps)
            uint32_t aH[4][4];
            #pragma unroll
            for (int mt = 0; mt < 4; mt++) {
                float4 af = *reinterpret_cast<const float4*>(
                    &Aperm[lane * LSTRIDE + mt * 64 + ks * 4]);
                aH[mt][0] = __float_as_uint(af.x);
                aH[mt][1] = __float_as_uint(af.y);
                aH[mt][2] = __float_as_uint(af.z);
                aH[mt][3] = __float_as_uint(af.w);
            }
            #pragma unroll
            for (int nt = 0; nt < 4; nt++)
                #pragma unroll
                for (int mt = 0; mt < 4; mt++)
                    MMA_TF32(acc[nt][mt], aH[mt], cb0[nt], cb1[nt]);
        }

        // ---- extra K-group: fold bias (k=0: -128 exact, k=1: -en2/2) ----
        #pragma unroll
        for (int nt = 0; nt < 4; nt++) {
            int code = n0 + nt * 8 + r_lane;
            uint32_t bh0 = 0u;
            if (c_lane == 0) bh0 = __float_as_uint(-128.0f);
            if (c_lane == 1) bh0 = __float_as_uint(__fmul_rn(-0.5f, en2s[code]));
            #pragma unroll
            for (int mt = 0; mt < 4; mt++)
                MMA_TF32(acc[nt][mt], aHe, bh0, 0u);
        }

        // ---- slim epilogue: s = -2*acc (>0), packed top-2 ----
        #pragma unroll
        for (int nt = 0; nt < 4; nt++) {
            int kk0 = n0 + nt * 8 + 2 * c_lane;
            #pragma unroll
            for (int mt = 0; mt < 4; mt++) {
                #pragma unroll
                for (int q = 0; q < 4; q++) {
                    int   h  = q >> 1;
                    int   kk = kk0 + (q & 1);
                    float s  = __fmul_rn(-2.0f, acc[nt][mt][q]);
                    unsigned long long p =
                        ((unsigned long long)__float_as_uint(s) << 32) | (unsigned)kk;
                    unsigned long long hi = umax64(b1[mt][h], p);
                    b1[mt][h] = umin64(b1[mt][h], p);
                    b2[mt][h] = umin64(b2[mt][h], hi);
                }
            }
        }
    }

    // ---- per-warp packed min per token row ----
    #pragma unroll
    for (int mt = 0; mt < 4; mt++)
        #pragma unroll
        for (int h = 0; h < 2; h++) {
            unsigned long long v = b1[mt][h];
            #pragma unroll
            for (int off = 1; off <= 2; off <<= 1)
                v = umin64(v, __shfl_xor_sync(0xffffffffu, v, off));
            if (c_lane == 0) redp[wid][mt * 16 + r_lane + 8 * h] = v;
        }
    __syncthreads();

    if (tid < BM) {
        unsigned long long v = redp[0][tid];
        #pragma unroll
        for (int w = 1; w < 8; w++) v = umin64(v, redp[w][tid]);
        minv[tid] = __uint_as_float((uint32_t)(v >> 32));   // min s
        cand[tid] = ~0ull;
    }
    __syncthreads();

    // ---- exact rescoring of candidates within MARGIN (s-domain cut) ----
    #pragma unroll
    for (int mt = 0; mt < 4; mt++)
        #pragma unroll
        for (int h = 0; h < 2; h++) {
            int row = mt * 16 + r_lane + 8 * h;
            float cut = minv[row] + MARGIN;
            const float4* srow4 = src4 + (size_t)row * (DIM / 4);
            float v1 = __uint_as_float((uint32_t)(b1[mt][h] >> 32));
            float v2 = __uint_as_float((uint32_t)(b2[mt][h] >> 32));
            if (v1 <= cut)
                rescore(srow4, embed, en2s, rn2s, cand, row,
                        (int)(unsigned)(b1[mt][h] & 0xFFFFFFFFull));
            if (v2 <= cut)
                rescore(srow4, embed, en2s, rn2s, cand, row,
                        (int)(unsigned)(b2[mt][h] & 0xFFFFFFFFull));
        }
    __syncthreads();

    if (tid < BM)
        idx_out[m0blk + tid] = (float)(unsigned)(cand[tid] & 0xFFFFFFFFull);
}

// ---------------------------------------------------------------------------
// residual: dst = src - gather(e[idx]), exact fsub. dst may alias src.
// ---------------------------------------------------------------------------
__global__ void __launch_bounds__(256)
residual_kernel(const float* __restrict__ src,
                const float* __restrict__ embed,
                const float* __restrict__ idx_lvl,
                float* __restrict__ dst,
                int early)
{
    if (early) return;
    int i = blockIdx.x * 256 + threadIdx.x;
    int row = i >> 5, c = i & 31;
    int k = __float2int_rn(idx_lvl[row]);
    float4 v = reinterpret_cast<const float4*>(src)[i];
    float4 e = reinterpret_cast<const float4*>(embed + (size_t)k * DIM)[c];
    v.x = __fsub_rn(v.x, e.x);
    v.y = __fsub_rn(v.y, e.y);
    v.z = __fsub_rn(v.z, e.z);
    v.w = __fsub_rn(v.w, e.w);
    reinterpret_cast<float4*>(dst)[i] = v;
}

__global__ void init3_kernel(float* __restrict__ out3, int early)
{
    if (early) return;
    if (threadIdx.x < 3) out3[threadIdx.x] = 0.f;
}

// ---------------------------------------------------------------------------
// final fused pass (unchanged from the validated R7 kernel)
// ---------------------------------------------------------------------------
__global__ void __launch_bounds__(256)
final_kernel(const float* __restrict__ inputs,
             const float* __restrict__ embedding,
             const float* __restrict__ idx_all,
             float* __restrict__ out_q,
             float* __restrict__ out3,
             int early)
{
    if (early) return;
    __shared__ float red[256];

    int tid = threadIdx.x;
    int d   = tid & 127;
    float acc = 0.f;

    #pragma unroll
    for (int it = 0; it < FINAL_ROWS / 2; it++) {
        int row = blockIdx.x * FINAL_ROWS + it * 2 + (tid >> 7);
        size_t o = (size_t)row * DIM + d;
        float inp = inputs[o];
        float r = inp, qs, e, diff;
        int k;

        k = __float2int_rn(idx_all[row]);
        e = embedding[((size_t)0 * NCODE + k) * DIM + d];
        diff = __fsub_rn(e, r); acc = fmaf(diff, diff, acc);
        qs = e; r = __fsub_rn(r, e);

        k = __float2int_rn(idx_all[(size_t)1 * NTOK + row]);
        e = embedding[((size_t)1 * NCODE + k) * DIM + d];
        diff = __fsub_rn(e, r); acc = fmaf(diff, diff, acc);
        qs = __fadd_rn(qs, e); r = __fsub_rn(r, e);

        k = __float2int_rn(idx_all[(size_t)2 * NTOK + row]);
        e = embedding[((size_t)2 * NCODE + k) * DIM + d];
        diff = __fsub_rn(e, r); acc = fmaf(diff, diff, acc);
        qs = __fadd_rn(qs, e); r = __fsub_rn(r, e);

        k = __float2int_rn(idx_all[(size_t)3 * NTOK + row]);
        e = embedding[((size_t)3 * NCODE + k) * DIM + d];
        diff = __fsub_rn(e, r); acc = fmaf(diff, diff, acc);
        qs = __fadd_rn(qs, e);

        out_q[o] = __fadd_rn(inp, __fsub_rn(qs, inp));
    }

    red[tid] = acc;
    __syncthreads();
    #pragma unroll
    for (int s = 128; s > 0; s >>= 1) {
        if (tid < s) red[tid] += red[tid + s];
        __syncthreads();
    }
    if (tid == 0) atomicAdd(&out3[1], red[0]);
}

__global__ void scalars_kernel(float* __restrict__ out3, int early)
{
    if (early) return;
    if (threadIdx.x == 0) {
        float cb = __fmul_rn(out3[1], 1.0f / 16777216.0f);
        out3[0] = __fadd_rn(cb, __fmul_rn(0.25f, cb));
        out3[1] = cb;
        out3[2] = cb;
    }
}

// ---------------------------------------------------------------------------
namespace {
struct ModuleEagerLoad {
    ModuleEagerLoad() {
        cudaFree(0);
        size_t f0 = 0, f1 = 0, tot = 0;
        cudaMemGetInfo(&f0, &tot);

        void* p;
        cudaGetSymbolAddress(&p, g_en2);

        prep_kernel<<<PREP_GRID, 256>>>(nullptr, 1);
        argmin_kernel<<<ARGMIN_GRID, 256>>>(nullptr, nullptr, nullptr, nullptr, 1);
        residual_kernel<<<RES_GRID, 256>>>(nullptr, nullptr, nullptr, nullptr, 1);
        init3_kernel<<<1, 32>>>(nullptr, 1);
        final_kernel<<<FINAL_GRID, 256>>>(nullptr, nullptr, nullptr, nullptr, nullptr, 1);
        scalars_kernel<<<1, 32>>>(nullptr, 1);
        cudaDeviceSynchronize();

        cudaMemGetInfo(&f1, &tot);
        fprintf(stderr, "[eager] free before=%zu after=%zu delta=%lld\n",
                f0, f1, (long long)f0 - (long long)f1);
    }
};
static ModuleEagerLoad s_eager_load;
}  // namespace

// ---------------------------------------------------------------------------
extern "C" void kernel_launch(void* const* d_in, const int* in_sizes, int n_in,
                              void* d_out, int out_size)
{
    const float* inputs    = (const float*)d_in[0];
    const float* embedding = (const float*)d_in[1];

    float* out     = (float*)d_out;
    float* out_q   = out;                            // N*D: residual scratch, then quantized_sum
    float* out_idx = out + (size_t)NTOK * DIM;       // L*N indices (as f32)
    float* out3    = out_idx + (size_t)NLVL * NTOK;  // vq, codebook, commit

    float* en2_base = nullptr;
    cudaGetSymbolAddress((void**)&en2_base, g_en2);

    init3_kernel<<<1, 32>>>(out3, 0);
    prep_kernel<<<PREP_GRID, 256>>>(embedding, 0);
    for (int lvl = 0; lvl < NLVL; lvl++) {
        const float* emb_l = embedding + (size_t)lvl * NCODE * DIM;
        const float* src   = (lvl == 0) ? inputs : out_q;
        argmin_kernel<<<ARGMIN_GRID, 256>>>(
            src, emb_l, en2_base + (size_t)lvl * NCODE,
            out_idx + (size_t)lvl * NTOK, 0);
        if (lvl < NLVL - 1)
            residual_kernel<<<RES_GRID, 256>>>(
                src, emb_l, out_idx + (size_t)lvl * NTOK, out_q, 0);
    }
    final_kernel<<<FINAL_GRID, 256>>>(inputs, embedding, out_idx, out_q, out3, 0);
    scalars_kernel<<<1, 32>>>(out3, 0);
}

// round 16
// speedup vs baseline: 1.4968x; 1.4968x over previous
#include <cuda_runtime.h>
#include <cuda_fp16.h>
#include <cstdint>
#include <cstdio>

#define NTOK  131072
#define DIM   128
#define NCODE 1024
#define NLVL  4

#define BM    64                 // tokens per CTA
#define ARGMIN_GRID (NTOK / BM)  // 2048
#define RES_GRID    (NTOK * (DIM / 4) / 256)     // 16384
#define FINAL_ROWS  16
#define FINAL_GRID  (NTOK / FINAL_ROWS)          // 8192
#define PREP_GRID   (NLVL * NCODE / 8)           // 512

#define MARGIN 2e-4f             // capture margin in s-domain

#define AST 132                  // Aperm per-lane stride (words): 132 % 32 == 4

// ---- small float-only device global (validated safe in R12) ----
__device__ float g_en2[NLVL * NCODE];   // 16 KB

// ---- fp16 tensor-core mma, m16n8k16 (sm_80+; compiles on sm_100 base) ----
#define MMA_F16(d, a, b0, b1)                                               \
    asm volatile("mma.sync.aligned.m16n8k16.row.col.f32.f16.f16.f32 "       \
        "{%0,%1,%2,%3}, {%4,%5,%6,%7}, {%8,%9}, {%0,%1,%2,%3};"             \
        : "+f"((d)[0]), "+f"((d)[1]), "+f"((d)[2]), "+f"((d)[3])            \
        : "r"((a)[0]), "r"((a)[1]), "r"((a)[2]), "r"((a)[3]),               \
          "r"(b0), "r"(b1))

// pack {lo, hi} floats -> f16x2 register (lo in low half)
__device__ __forceinline__ uint32_t pack_h2(float lo, float hi)
{
    uint32_t r;
    asm("cvt.rn.f16x2.f32 %0, %1, %2;" : "=r"(r) : "f"(hi), "f"(lo));
    return r;
}

__device__ __forceinline__ unsigned long long umin64(unsigned long long a,
                                                     unsigned long long b)
{ return a < b ? a : b; }
__device__ __forceinline__ unsigned long long umax64(unsigned long long a,
                                                     unsigned long long b)
{ return a > b ? a : b; }

// ---------------------------------------------------------------------------
// prep: en2[r] = sum_d e[r][d]^2 for ALL levels (bit-identical R7 formula).
// ---------------------------------------------------------------------------
__global__ void __launch_bounds__(256)
prep_kernel(const float* __restrict__ embedding, int early)
{
    if (early) return;
    int lane = threadIdx.x & 31;
    int row  = blockIdx.x * 8 + (threadIdx.x >> 5);   // 0..4095
    float4 v = reinterpret_cast<const float4*>(embedding + (size_t)row * DIM)[lane];
    float p = __fadd_rn(__fadd_rn(__fadd_rn(__fmul_rn(v.x, v.x),
                                            __fmul_rn(v.y, v.y)),
                                  __fmul_rn(v.z, v.z)),
                        __fmul_rn(v.w, v.w));
    #pragma unroll
    for (int off = 16; off >= 1; off >>= 1)
        p = __fadd_rn(p, __shfl_down_sync(0xffffffffu, p, off));
    if (lane == 0) g_en2[row] = p;
}

// exact R7-bit-identical rescore: sequential-d fp32 fmaf dot + binned dist;
// lowest-index tie-break via packed u64 atomicMin (exact dist domain).
__device__ __forceinline__ void rescore(const float4* __restrict__ srow4,
                                        const float* __restrict__ embed,
                                        const float* en2s, const float* rn2s,
                                        unsigned long long* cand,
                                        int row, int k)
{
    const float4* e4 = reinterpret_cast<const float4*>(embed + (size_t)k * DIM);
    float dot = 0.f;
    #pragma unroll 8
    for (int i = 0; i < 32; i++) {
        float4 a = __ldg(srow4 + i);
        float4 e = __ldg(e4 + i);
        dot = fmaf(a.x, e.x, dot);
        dot = fmaf(a.y, e.y, dot);
        dot = fmaf(a.z, e.z, dot);
        dot = fmaf(a.w, e.w, dot);
    }
    float dist = __fsub_rn(__fadd_rn(rn2s[row], en2s[k]), __fmul_rn(2.0f, dot));
    unsigned long long p =
        ((unsigned long long)__float_as_uint(dist) << 32) | (unsigned)k;
    atomicMin(cand + row, p);
}

// ---------------------------------------------------------------------------
// argmin (R13 structure, fp16 m16n8k16 engine): 4 warps x 256 codes, Aperm
// smem fragment-major f16x2, bias folded into the GEMM, exact top-2 rescore.
// ---------------------------------------------------------------------------
__global__ void __launch_bounds__(128)
argmin_kernel(const float* __restrict__ src,     // N x D (inputs or residual)
              const float* __restrict__ embed,   // K x D, this level (fp32)
              const float* __restrict__ en2g,    // K, this level (from g_en2)
              float* __restrict__ idx_out,       // N floats, this level slice
              int early)
{
    if (early) return;

    __shared__ uint32_t Aperm[32 * AST];         // 16.9 KB fragment-major f16x2
    __shared__ float en2s[NCODE];                // 4 KB
    __shared__ float rn2s[BM];
    __shared__ unsigned long long redp[4][BM];   // per-warp packed approx min
    __shared__ float minv[BM];
    __shared__ unsigned long long cand[BM];

    const int tid  = threadIdx.x;
    const int wid  = tid >> 5, lane = tid & 31;
    const int m0blk = blockIdx.x * BM;
    const float4* __restrict__ src4 =
        reinterpret_cast<const float4*>(src) + (size_t)m0blk * (DIM / 4);

    // ---- en2 slice: global -> smem (coalesced float4) ----
    {
        const float4* g4 = reinterpret_cast<const float4*>(en2g);
        float4* s4 = reinterpret_cast<float4*>(en2s);
        for (int j = tid; j < NCODE / 4; j += 128) s4[j] = __ldg(g4 + j);
    }

    // ---- A panel -> Aperm (fp16x2 pairs, mma-fragment-major layout) ----
    // fragment map (m16n8k16 A, row.col): lane=(g=lane>>2, t=lane&3)
    //   a0=(g, 2t..2t+1) a1=(g+8, ..) a2=(g, 2t+8..9) a3=(g+8, ..)
    #pragma unroll
    for (int i = 0; i < 16; i++) {
        int flat = tid + i * 128;
        int row = flat >> 5, c4 = flat & 31;     // cols 4c4..4c4+3
        float4 v = src4[(size_t)row * (DIM / 4) + c4];
        int ks = c4 >> 2;                        // 16 cols per k-step
        int mt = row >> 4;
        int r = row & 15, rowhalf = r >> 3, g = r & 7;
        int pp0 = 2 * (c4 & 3), pp1 = pp0 + 1;   // pair idx within k16 (0..7)
        uint32_t w0 = pack_h2(v.x, v.y);
        uint32_t w1 = pack_h2(v.z, v.w);
        int t0 = pp0 & 3, q0 = ((pp0 >> 2) << 1) + rowhalf;
        int t1 = pp1 & 3, q1 = ((pp1 >> 2) << 1) + rowhalf;
        Aperm[(4 * g + t0) * AST + mt * 32 + ks * 4 + q0] = w0;
        Aperm[(4 * g + t1) * AST + mt * 32 + ks * 4 + q1] = w1;
    }

    // ---- rn2 from EXACT global values: bit-identical to R7 ----
    for (int r = wid; r < BM; r += 4) {
        float4 v = src4[(size_t)r * (DIM / 4) + lane];
        float p = __fadd_rn(__fadd_rn(__fadd_rn(__fmul_rn(v.x, v.x),
                                                __fmul_rn(v.y, v.y)),
                                      __fmul_rn(v.z, v.z)),
                            __fmul_rn(v.w, v.w));
        #pragma unroll
        for (int off = 16; off >= 1; off >>= 1)
            p = __fadd_rn(p, __shfl_down_sync(0xffffffffu, p, off));
        if (lane == 0) rn2s[r] = p;
    }
    __syncthreads();

    const int g_lane = lane >> 2;   // 0..7 (token-row group / code group)
    const int t_lane = lane & 3;    // 0..3 (k group / D-column pair)
    const int n_warp0 = wid * 256;  // this warp's code range

    // extra-K fragments (bias): a = {1, 2^-5} at k-pair 0 (t==0 only)
    uint32_t aHe[4];
    aHe[0] = aHe[1] = (t_lane == 0) ? pack_h2(1.0f, 0.03125f) : 0u;
    aHe[2] = aHe[3] = 0u;

    // per-thread packed top-2 in s-domain (s bits<<32 | idx)
    unsigned long long b1[4][2], b2[4][2];
    #pragma unroll
    for (int mt = 0; mt < 4; mt++)
        #pragma unroll
        for (int h = 0; h < 2; h++) { b1[mt][h] = ~0ull; b2[mt][h] = ~0ull; }

    for (int nblk = 0; nblk < 8; nblk++) {
        const int n0 = n_warp0 + nblk * 32;

        float acc[4][4][4];   // [nt][mt][frag]
        #pragma unroll
        for (int nt = 0; nt < 4; nt++)
            #pragma unroll
            for (int mt = 0; mt < 4; mt++)
                #pragma unroll
                for (int q = 0; q < 4; q++) acc[nt][mt][q] = 0.f;

        #pragma unroll
        for (int ks = 0; ks < 8; ks++) {
            // A fragments: one LDS.128 per mt (broadcast across warps)
            uint32_t aH[4][4];
            #pragma unroll
            for (int mt = 0; mt < 4; mt++) {
                uint4 af = *reinterpret_cast<const uint4*>(
                    &Aperm[lane * AST + mt * 32 + ks * 4]);
                aH[mt][0] = af.x; aH[mt][1] = af.y;
                aH[mt][2] = af.z; aH[mt][3] = af.w;
            }
            #pragma unroll
            for (int nt = 0; nt < 4; nt++) {
                int code = n0 + nt * 8 + g_lane;
                const float* ep = embed + (size_t)code * DIM + ks * 16 + 2 * t_lane;
                float2 e0 = __ldg(reinterpret_cast<const float2*>(ep));
                float2 e1 = __ldg(reinterpret_cast<const float2*>(ep + 8));
                uint32_t bh0 = pack_h2(e0.x, e0.y);
                uint32_t bh1 = pack_h2(e1.x, e1.y);
                #pragma unroll
                for (int mt = 0; mt < 4; mt++)
                    MMA_F16(acc[nt][mt], aH[mt], bh0, bh1);
            }
        }

        // ---- extra K-group: bias fold, b = {-128, -16*en2} at t==0 ----
        #pragma unroll
        for (int nt = 0; nt < 4; nt++) {
            int code = n0 + nt * 8 + g_lane;
            uint32_t bh0 = (t_lane == 0)
                ? pack_h2(-128.0f, __fmul_rn(-16.0f, en2s[code])) : 0u;
            #pragma unroll
            for (int mt = 0; mt < 4; mt++)
                MMA_F16(acc[nt][mt], aHe, bh0, 0u);
        }

        // ---- slim epilogue: s = -2*acc (>0), packed top-2 ----
        #pragma unroll
        for (int nt = 0; nt < 4; nt++) {
            int kk0 = n0 + nt * 8 + 2 * t_lane;
            #pragma unroll
            for (int mt = 0; mt < 4; mt++) {
                #pragma unroll
                for (int q = 0; q < 4; q++) {
                    int   h  = q >> 1;               // 0: row g, 1: row g+8
                    int   kk = kk0 + (q & 1);
                    float s  = __fmul_rn(-2.0f, acc[nt][mt][q]);
                    unsigned long long p =
                        ((unsigned long long)__float_as_uint(s) << 32) | (unsigned)kk;
                    unsigned long long hi = umax64(b1[mt][h], p);
                    b1[mt][h] = umin64(b1[mt][h], p);
                    b2[mt][h] = umin64(b2[mt][h], hi);
                }
            }
        }
    }

    // ---- per-warp packed min per token row ----
    #pragma unroll
    for (int mt = 0; mt < 4; mt++)
        #pragma unroll
        for (int h = 0; h < 2; h++) {
            unsigned long long v = b1[mt][h];
            #pragma unroll
            for (int off = 1; off <= 2; off <<= 1)
                v = umin64(v, __shfl_xor_sync(0xffffffffu, v, off));
            if (t_lane == 0) redp[wid][mt * 16 + g_lane + 8 * h] = v;
        }
    __syncthreads();

    if (tid < BM) {
        unsigned long long v = redp[0][tid];
        #pragma unroll
        for (int w = 1; w < 4; w++) v = umin64(v, redp[w][tid]);
        minv[tid] = __uint_as_float((uint32_t)(v >> 32));   // min s
        cand[tid] = ~0ull;
    }
    __syncthreads();

    // ---- exact rescoring of candidates within MARGIN (s-domain cut) ----
    #pragma unroll
    for (int mt = 0; mt < 4; mt++)
        #pragma unroll
        for (int h = 0; h < 2; h++) {
            int row = mt * 16 + g_lane + 8 * h;
            float cut = minv[row] + MARGIN;
            const float4* srow4 = src4 + (size_t)row * (DIM / 4);
            float v1 = __uint_as_float((uint32_t)(b1[mt][h] >> 32));
            float v2 = __uint_as_float((uint32_t)(b2[mt][h] >> 32));
            if (v1 <= cut)
                rescore(srow4, embed, en2s, rn2s, cand, row,
                        (int)(unsigned)(b1[mt][h] & 0xFFFFFFFFull));
            if (v2 <= cut)
                rescore(srow4, embed, en2s, rn2s, cand, row,
                        (int)(unsigned)(b2[mt][h] & 0xFFFFFFFFull));
        }
    __syncthreads();

    if (tid < BM)
        idx_out[m0blk + tid] = (float)(unsigned)(cand[tid] & 0xFFFFFFFFull);
}

// ---------------------------------------------------------------------------
// residual: dst = src - gather(e[idx]), exact fsub. dst may alias src.
// ---------------------------------------------------------------------------
__global__ void __launch_bounds__(256)
residual_kernel(const float* __restrict__ src,
                const float* __restrict__ embed,
                const float* __restrict__ idx_lvl,
                float* __restrict__ dst,
                int early)
{
    if (early) return;
    int i = blockIdx.x * 256 + threadIdx.x;
    int row = i >> 5, c = i & 31;
    int k = __float2int_rn(idx_lvl[row]);
    float4 v = reinterpret_cast<const float4*>(src)[i];
    float4 e = reinterpret_cast<const float4*>(embed + (size_t)k * DIM)[c];
    v.x = __fsub_rn(v.x, e.x);
    v.y = __fsub_rn(v.y, e.y);
    v.z = __fsub_rn(v.z, e.z);
    v.w = __fsub_rn(v.w, e.w);
    reinterpret_cast<float4*>(dst)[i] = v;
}

__global__ void init3_kernel(float* __restrict__ out3, int early)
{
    if (early) return;
    if (threadIdx.x < 3) out3[threadIdx.x] = 0.f;
}

// ---------------------------------------------------------------------------
// final fused pass (unchanged from the validated R7 kernel)
// ---------------------------------------------------------------------------
__global__ void __launch_bounds__(256)
final_kernel(const float* __restrict__ inputs,
             const float* __restrict__ embedding,
             const float* __restrict__ idx_all,
             float* __restrict__ out_q,
             float* __restrict__ out3,
             int early)
{
    if (early) return;
    __shared__ float red[256];

    int tid = threadIdx.x;
    int d   = tid & 127;
    float acc = 0.f;

    #pragma unroll
    for (int it = 0; it < FINAL_ROWS / 2; it++) {
        int row = blockIdx.x * FINAL_ROWS + it * 2 + (tid >> 7);
        size_t o = (size_t)row * DIM + d;
        float inp = inputs[o];
        float r = inp, qs, e, diff;
        int k;

        k = __float2int_rn(idx_all[row]);
        e = embedding[((size_t)0 * NCODE + k) * DIM + d];
        diff = __fsub_rn(e, r); acc = fmaf(diff, diff, acc);
        qs = e; r = __fsub_rn(r, e);

        k = __float2int_rn(idx_all[(size_t)1 * NTOK + row]);
        e = embedding[((size_t)1 * NCODE + k) * DIM + d];
        diff = __fsub_rn(e, r); acc = fmaf(diff, diff, acc);
        qs = __fadd_rn(qs, e); r = __fsub_rn(r, e);

        k = __float2int_rn(idx_all[(size_t)2 * NTOK + row]);
        e = embedding[((size_t)2 * NCODE + k) * DIM + d];
        diff = __fsub_rn(e, r); acc = fmaf(diff, diff, acc);
        qs = __fadd_rn(qs, e); r = __fsub_rn(r, e);

        k = __float2int_rn(idx_all[(size_t)3 * NTOK + row]);
        e = embedding[((size_t)3 * NCODE + k) * DIM + d];
        diff = __fsub_rn(e, r); acc = fmaf(diff, diff, acc);
        qs = __fadd_rn(qs, e);

        out_q[o] = __fadd_rn(inp, __fsub_rn(qs, inp));
    }

    red[tid] = acc;
    __syncthreads();
    #pragma unroll
    for (int s = 128; s > 0; s >>= 1) {
        if (tid < s) red[tid] += red[tid + s];
        __syncthreads();
    }
    if (tid == 0) atomicAdd(&out3[1], red[0]);
}

__global__ void scalars_kernel(float* __restrict__ out3, int early)
{
    if (early) return;
    if (threadIdx.x == 0) {
        float cb = __fmul_rn(out3[1], 1.0f / 16777216.0f);
        out3[0] = __fadd_rn(cb, __fmul_rn(0.25f, cb));
        out3[1] = cb;
        out3[2] = cb;
    }
}

// ---------------------------------------------------------------------------
namespace {
struct ModuleEagerLoad {
    ModuleEagerLoad() {
        cudaFree(0);
        size_t f0 = 0, f1 = 0, tot = 0;
        cudaMemGetInfo(&f0, &tot);

        void* p;
        cudaGetSymbolAddress(&p, g_en2);

        prep_kernel<<<PREP_GRID, 256>>>(nullptr, 1);
        argmin_kernel<<<ARGMIN_GRID, 128>>>(nullptr, nullptr, nullptr, nullptr, 1);
        residual_kernel<<<RES_GRID, 256>>>(nullptr, nullptr, nullptr, nullptr, 1);
        init3_kernel<<<1, 32>>>(nullptr, 1);
        final_kernel<<<FINAL_GRID, 256>>>(nullptr, nullptr, nullptr, nullptr, nullptr, 1);
        scalars_kernel<<<1, 32>>>(nullptr, 1);
        cudaDeviceSynchronize();

        cudaMemGetInfo(&f1, &tot);
        fprintf(stderr, "[eager] free before=%zu after=%zu delta=%lld\n",
                f0, f1, (long long)f0 - (long long)f1);
    }
};
static ModuleEagerLoad s_eager_load;
}  // namespace

// ---------------------------------------------------------------------------
extern "C" void kernel_launch(void* const* d_in, const int* in_sizes, int n_in,
                              void* d_out, int out_size)
{
    const float* inputs    = (const float*)d_in[0];
    const float* embedding = (const float*)d_in[1];

    float* out     = (float*)d_out;
    float* out_q   = out;                            // N*D: residual scratch, then quantized_sum
    float* out_idx = out + (size_t)NTOK * DIM;       // L*N indices (as f32)
    float* out3    = out_idx + (size_t)NLVL * NTOK;  // vq, codebook, commit

    float* en2_base = nullptr;
    cudaGetSymbolAddress((void**)&en2_base, g_en2);

    init3_kernel<<<1, 32>>>(out3, 0);
    prep_kernel<<<PREP_GRID, 256>>>(embedding, 0);
    for (int lvl = 0; lvl < NLVL; lvl++) {
        const float* emb_l = embedding + (size_t)lvl * NCODE * DIM;
        const float* src   = (lvl == 0) ? inputs : out_q;
        argmin_kernel<<<ARGMIN_GRID, 128>>>(
            src, emb_l, en2_base + (size_t)lvl * NCODE,
            out_idx + (size_t)lvl * NTOK, 0);
        if (lvl < NLVL - 1)
            residual_kernel<<<RES_GRID, 256>>>(
                src, emb_l, out_idx + (size_t)lvl * NTOK, out_q, 0);
    }
    final_kernel<<<FINAL_GRID, 256>>>(inputs, embedding, out_idx, out_q, out3, 0);
    scalars_kernel<<<1, 32>>>(out3, 0);
}

// round 17
// speedup vs baseline: 1.8948x; 1.2659x over previous
#include <cuda_runtime.h>
#include <cuda_fp16.h>
#include <cstdint>
#include <cstdio>

#define NTOK  131072
#define DIM   128
#define NCODE 1024
#define NLVL  4

#define BM    64                 // tokens per CTA
#define ARGMIN_GRID (NTOK / BM)  // 2048
#define RES_GRID    (NTOK * (DIM / 4) / 256)     // 16384
#define FINAL_ROWS  16
#define FINAL_GRID  (NTOK / FINAL_ROWS)          // 8192
#define PREP_GRID   (NLVL * NCODE / 8)           // 512

#define SBASE 0x437F0000u        // float bits of 255.0 (s is always > 255.6)
#define MARGIN_PACKED (16u << 10)  // ~4.9e-4 in s-domain

#define AST 132                  // Aperm per-lane stride (words): 132 % 32 == 4

// ---- device globals (float/half only; fp64 is what broke R1-R6) ----
__device__ float    g_en2[NLVL * NCODE];          // 16 KB
__device__ uint32_t g_emb16[NLVL * NCODE * 64];   // 2 MB: codebook as f16x2

// ---- fp16 tensor-core mma, m16n8k16 (sm_80+; compiles on sm_100 base) ----
#define MMA_F16(d, a, b0, b1)                                               \
    asm volatile("mma.sync.aligned.m16n8k16.row.col.f32.f16.f16.f32 "       \
        "{%0,%1,%2,%3}, {%4,%5,%6,%7}, {%8,%9}, {%0,%1,%2,%3};"             \
        : "+f"((d)[0]), "+f"((d)[1]), "+f"((d)[2]), "+f"((d)[3])            \
        : "r"((a)[0]), "r"((a)[1]), "r"((a)[2]), "r"((a)[3]),               \
          "r"(b0), "r"(b1))

// pack {lo, hi} floats -> f16x2 register (lo in low half)
__device__ __forceinline__ uint32_t pack_h2(float lo, float hi)
{
    uint32_t r;
    asm("cvt.rn.f16x2.f32 %0, %1, %2;" : "=r"(r) : "f"(hi), "f"(lo));
    return r;
}

// ---------------------------------------------------------------------------
// prep: en2 (bit-identical R7 formula) + fp16 codebook conversion, per launch.
// ---------------------------------------------------------------------------
__global__ void __launch_bounds__(256)
prep_kernel(const float* __restrict__ embedding, int early)
{
    if (early) return;
    int lane = threadIdx.x & 31;
    int row  = blockIdx.x * 8 + (threadIdx.x >> 5);   // 0..4095
    float4 v = reinterpret_cast<const float4*>(embedding + (size_t)row * DIM)[lane];

    // fp16 conversion: 4 floats -> 2 f16x2 words
    reinterpret_cast<uint2*>(g_emb16)[(size_t)row * 32 + lane] =
        make_uint2(pack_h2(v.x, v.y), pack_h2(v.z, v.w));

    float p = __fadd_rn(__fadd_rn(__fadd_rn(__fmul_rn(v.x, v.x),
                                            __fmul_rn(v.y, v.y)),
                                  __fmul_rn(v.z, v.z)),
                        __fmul_rn(v.w, v.w));
    #pragma unroll
    for (int off = 16; off >= 1; off >>= 1)
        p = __fadd_rn(p, __shfl_down_sync(0xffffffffu, p, off));
    if (lane == 0) g_en2[row] = p;
}

// exact R7-bit-identical rescore: sequential-d fp32 fmaf dot + binned dist;
// lowest-index tie-break via packed u64 atomicMin (exact dist domain).
__device__ __forceinline__ void rescore(const float4* __restrict__ srow4,
                                        const float* __restrict__ embed,
                                        const float* en2s, const float* rn2s,
                                        unsigned long long* cand,
                                        int row, int k)
{
    const float4* e4 = reinterpret_cast<const float4*>(embed + (size_t)k * DIM);
    float dot = 0.f;
    #pragma unroll 8
    for (int i = 0; i < 32; i++) {
        float4 a = __ldg(srow4 + i);
        float4 e = __ldg(e4 + i);
        dot = fmaf(a.x, e.x, dot);
        dot = fmaf(a.y, e.y, dot);
        dot = fmaf(a.z, e.z, dot);
        dot = fmaf(a.w, e.w, dot);
    }
    float dist = __fsub_rn(__fadd_rn(rn2s[row], en2s[k]), __fmul_rn(2.0f, dot));
    unsigned long long p =
        ((unsigned long long)__float_as_uint(dist) << 32) | (unsigned)k;
    atomicMin(cand + row, p);
}

// ---------------------------------------------------------------------------
// argmin (R16 structure): fp16 m16n8k16, pre-converted fp16 B, and a 32-bit
// packed top-2 epilogue (6 instr/element). Exact rescoring unchanged.
// ---------------------------------------------------------------------------
__global__ void __launch_bounds__(128)
argmin_kernel(const float* __restrict__ src,     // N x D (inputs or residual)
              const float* __restrict__ embed,   // K x D, this level (fp32)
              const uint32_t* __restrict__ embh, // K x 64, this level (f16x2)
              const float* __restrict__ en2g,    // K, this level (from g_en2)
              float* __restrict__ idx_out,       // N floats, this level slice
              int early)
{
    if (early) return;

    __shared__ uint32_t Aperm[32 * AST];         // 16.9 KB fragment-major f16x2
    __shared__ float en2s[NCODE];                // 4 KB
    __shared__ float rn2s[BM];
    __shared__ uint32_t redp[4][BM];             // per-warp packed approx min
    __shared__ uint32_t minp[BM];
    __shared__ unsigned long long cand[BM];

    const int tid  = threadIdx.x;
    const int wid  = tid >> 5, lane = tid & 31;
    const int m0blk = blockIdx.x * BM;
    const float4* __restrict__ src4 =
        reinterpret_cast<const float4*>(src) + (size_t)m0blk * (DIM / 4);

    // ---- en2 slice: global -> smem (coalesced float4) ----
    {
        const float4* g4 = reinterpret_cast<const float4*>(en2g);
        float4* s4 = reinterpret_cast<float4*>(en2s);
        for (int j = tid; j < NCODE / 4; j += 128) s4[j] = __ldg(g4 + j);
    }

    // ---- A panel -> Aperm (fp16x2 pairs, mma-fragment-major; R16-verbatim) ----
    #pragma unroll
    for (int i = 0; i < 16; i++) {
        int flat = tid + i * 128;
        int row = flat >> 5, c4 = flat & 31;     // cols 4c4..4c4+3
        float4 v = src4[(size_t)row * (DIM / 4) + c4];
        int ks = c4 >> 2;                        // 16 cols per k-step
        int mt = row >> 4;
        int r = row & 15, rowhalf = r >> 3, g = r & 7;
        int pp0 = 2 * (c4 & 3), pp1 = pp0 + 1;   // pair idx within k16 (0..7)
        uint32_t w0 = pack_h2(v.x, v.y);
        uint32_t w1 = pack_h2(v.z, v.w);
        int t0 = pp0 & 3, q0 = ((pp0 >> 2) << 1) + rowhalf;
        int t1 = pp1 & 3, q1 = ((pp1 >> 2) << 1) + rowhalf;
        Aperm[(4 * g + t0) * AST + mt * 32 + ks * 4 + q0] = w0;
        Aperm[(4 * g + t1) * AST + mt * 32 + ks * 4 + q1] = w1;
    }

    // ---- rn2 from EXACT global values: bit-identical to R7 ----
    for (int r = wid; r < BM; r += 4) {
        float4 v = src4[(size_t)r * (DIM / 4) + lane];
        float p = __fadd_rn(__fadd_rn(__fadd_rn(__fmul_rn(v.x, v.x),
                                                __fmul_rn(v.y, v.y)),
                                      __fmul_rn(v.z, v.z)),
                            __fmul_rn(v.w, v.w));
        #pragma unroll
        for (int off = 16; off >= 1; off >>= 1)
            p = __fadd_rn(p, __shfl_down_sync(0xffffffffu, p, off));
        if (lane == 0) rn2s[r] = p;
    }
    __syncthreads();

    const int g_lane = lane >> 2;   // 0..7 (token-row group / code group)
    const int t_lane = lane & 3;    // 0..3 (k group / D-column pair)
    const int n_warp0 = wid * 256;  // this warp's code range

    // extra-K fragments (bias): a = {1, 2^-5} at k-pair 0 (t==0 only)
    uint32_t aHe[4];
    aHe[0] = aHe[1] = (t_lane == 0) ? pack_h2(1.0f, 0.03125f) : 0u;
    aHe[2] = aHe[3] = 0u;

    // per-thread packed top-2 (u32): ((s_bits - SBASE) << 10) | idx
    uint32_t b1[4][2], b2[4][2];
    #pragma unroll
    for (int mt = 0; mt < 4; mt++)
        #pragma unroll
        for (int h = 0; h < 2; h++) { b1[mt][h] = ~0u; b2[mt][h] = ~0u; }

    for (int nblk = 0; nblk < 8; nblk++) {
        const int n0 = n_warp0 + nblk * 32;

        float acc[4][4][4];   // [nt][mt][frag]
        #pragma unroll
        for (int nt = 0; nt < 4; nt++)
            #pragma unroll
            for (int mt = 0; mt < 4; mt++)
                #pragma unroll
                for (int q = 0; q < 4; q++) acc[nt][mt][q] = 0.f;

        #pragma unroll
        for (int ks = 0; ks < 8; ks++) {
            // A fragments: one LDS.128 per mt (broadcast across warps)
            uint32_t aH[4][4];
            #pragma unroll
            for (int mt = 0; mt < 4; mt++) {
                uint4 af = *reinterpret_cast<const uint4*>(
                    &Aperm[lane * AST + mt * 32 + ks * 4]);
                aH[mt][0] = af.x; aH[mt][1] = af.y;
                aH[mt][2] = af.z; aH[mt][3] = af.w;
            }
            #pragma unroll
            for (int nt = 0; nt < 4; nt++) {
                int code = n0 + nt * 8 + g_lane;
                const uint32_t* bp = embh + (size_t)code * 64 + ks * 8 + t_lane;
                uint32_t bh0 = __ldg(bp);        // pre-converted f16x2
                uint32_t bh1 = __ldg(bp + 4);
                #pragma unroll
                for (int mt = 0; mt < 4; mt++)
                    MMA_F16(acc[nt][mt], aH[mt], bh0, bh1);
            }
        }

        // ---- extra K-group: bias fold, b = {-128, -16*en2} at t==0 ----
        #pragma unroll
        for (int nt = 0; nt < 4; nt++) {
            int code = n0 + nt * 8 + g_lane;
            uint32_t bh0 = (t_lane == 0)
                ? pack_h2(-128.0f, __fmul_rn(-16.0f, en2s[code])) : 0u;
            #pragma unroll
            for (int mt = 0; mt < 4; mt++)
                MMA_F16(acc[nt][mt], aHe, bh0, 0u);
        }

        // ---- packed-u32 top-2 epilogue: 6 instr per element ----
        #pragma unroll
        for (int nt = 0; nt < 4; nt++) {
            int kk0 = n0 + nt * 8 + 2 * t_lane;
            #pragma unroll
            for (int mt = 0; mt < 4; mt++) {
                #pragma unroll
                for (int q = 0; q < 4; q++) {
                    int   h  = q >> 1;               // 0: row g, 1: row g+8
                    int   kk = kk0 + (q & 1);
                    float s  = __fmul_rn(-2.0f, acc[nt][mt][q]);
                    uint32_t d = __float_as_uint(s) - SBASE;  // 17-bit, monotone
                    uint32_t p = (d << 10) | (uint32_t)kk;
                    uint32_t hi = max(b1[mt][h], p);
                    b1[mt][h] = min(b1[mt][h], p);
                    b2[mt][h] = min(b2[mt][h], hi);
                }
            }
        }
    }

    // ---- per-warp packed min per token row ----
    #pragma unroll
    for (int mt = 0; mt < 4; mt++)
        #pragma unroll
        for (int h = 0; h < 2; h++) {
            uint32_t v = b1[mt][h];
            #pragma unroll
            for (int off = 1; off <= 2; off <<= 1)
                v = min(v, __shfl_xor_sync(0xffffffffu, v, off));
            if (t_lane == 0) redp[wid][mt * 16 + g_lane + 8 * h] = v;
        }
    __syncthreads();

    if (tid < BM) {
        uint32_t v = redp[0][tid];
        #pragma unroll
        for (int w = 1; w < 4; w++) v = min(v, redp[w][tid]);
        minp[tid] = v;
        cand[tid] = ~0ull;
    }
    __syncthreads();

    // ---- exact rescoring of candidates within margin (packed-domain cut) ----
    #pragma unroll
    for (int mt = 0; mt < 4; mt++)
        #pragma unroll
        for (int h = 0; h < 2; h++) {
            int row = mt * 16 + g_lane + 8 * h;
            uint32_t cut = minp[row] + MARGIN_PACKED;
            const float4* srow4 = src4 + (size_t)row * (DIM / 4);
            if (b1[mt][h] <= cut)
                rescore(srow4, embed, en2s, rn2s, cand, row,
                        (int)(b1[mt][h] & 1023u));
            if (b2[mt][h] <= cut)
                rescore(srow4, embed, en2s, rn2s, cand, row,
                        (int)(b2[mt][h] & 1023u));
        }
    __syncthreads();

    if (tid < BM)
        idx_out[m0blk + tid] = (float)(unsigned)(cand[tid] & 0xFFFFFFFFull);
}

// ---------------------------------------------------------------------------
// residual: dst = src - gather(e[idx]), exact fsub. dst may alias src.
// ---------------------------------------------------------------------------
__global__ void __launch_bounds__(256)
residual_kernel(const float* __restrict__ src,
                const float* __restrict__ embed,
                const float* __restrict__ idx_lvl,
                float* __restrict__ dst,
                int early)
{
    if (early) return;
    int i = blockIdx.x * 256 + threadIdx.x;
    int row = i >> 5, c = i & 31;
    int k = __float2int_rn(idx_lvl[row]);
    float4 v = reinterpret_cast<const float4*>(src)[i];
    float4 e = reinterpret_cast<const float4*>(embed + (size_t)k * DIM)[c];
    v.x = __fsub_rn(v.x, e.x);
    v.y = __fsub_rn(v.y, e.y);
    v.z = __fsub_rn(v.z, e.z);
    v.w = __fsub_rn(v.w, e.w);
    reinterpret_cast<float4*>(dst)[i] = v;
}

__global__ void init3_kernel(float* __restrict__ out3, int early)
{
    if (early) return;
    if (threadIdx.x < 3) out3[threadIdx.x] = 0.f;
}

// ---------------------------------------------------------------------------
// final fused pass (unchanged from the validated R7 kernel)
// ---------------------------------------------------------------------------
__global__ void __launch_bounds__(256)
final_kernel(const float* __restrict__ inputs,
             const float* __restrict__ embedding,
             const float* __restrict__ idx_all,
             float* __restrict__ out_q,
             float* __restrict__ out3,
             int early)
{
    if (early) return;
    __shared__ float red[256];

    int tid = threadIdx.x;
    int d   = tid & 127;
    float acc = 0.f;

    #pragma unroll
    for (int it = 0; it < FINAL_ROWS / 2; it++) {
        int row = blockIdx.x * FINAL_ROWS + it * 2 + (tid >> 7);
        size_t o = (size_t)row * DIM + d;
        float inp = inputs[o];
        float r = inp, qs, e, diff;
        int k;

        k = __float2int_rn(idx_all[row]);
        e = embedding[((size_t)0 * NCODE + k) * DIM + d];
        diff = __fsub_rn(e, r); acc = fmaf(diff, diff, acc);
        qs = e; r = __fsub_rn(r, e);

        k = __float2int_rn(idx_all[(size_t)1 * NTOK + row]);
        e = embedding[((size_t)1 * NCODE + k) * DIM + d];
        diff = __fsub_rn(e, r); acc = fmaf(diff, diff, acc);
        qs = __fadd_rn(qs, e); r = __fsub_rn(r, e);

        k = __float2int_rn(idx_all[(size_t)2 * NTOK + row]);
        e = embedding[((size_t)2 * NCODE + k) * DIM + d];
        diff = __fsub_rn(e, r); acc = fmaf(diff, diff, acc);
        qs = __fadd_rn(qs, e); r = __fsub_rn(r, e);

        k = __float2int_rn(idx_all[(size_t)3 * NTOK + row]);
        e = embedding[((size_t)3 * NCODE + k) * DIM + d];
        diff = __fsub_rn(e, r); acc = fmaf(diff, diff, acc);
        qs = __fadd_rn(qs, e);

        out_q[o] = __fadd_rn(inp, __fsub_rn(qs, inp));
    }

    red[tid] = acc;
    __syncthreads();
    #pragma unroll
    for (int s = 128; s > 0; s >>= 1) {
        if (tid < s) red[tid] += red[tid + s];
        __syncthreads();
    }
    if (tid == 0) atomicAdd(&out3[1], red[0]);
}

__global__ void scalars_kernel(float* __restrict__ out3, int early)
{
    if (early) return;
    if (threadIdx.x == 0) {
        float cb = __fmul_rn(out3[1], 1.0f / 16777216.0f);
        out3[0] = __fadd_rn(cb, __fmul_rn(0.25f, cb));
        out3[1] = cb;
        out3[2] = cb;
    }
}

// ---------------------------------------------------------------------------
namespace {
struct ModuleEagerLoad {
    ModuleEagerLoad() {
        cudaFree(0);
        size_t f0 = 0, f1 = 0, tot = 0;
        cudaMemGetInfo(&f0, &tot);

        void* p;
        cudaGetSymbolAddress(&p, g_en2);
        cudaGetSymbolAddress(&p, g_emb16);

        prep_kernel<<<PREP_GRID, 256>>>(nullptr, 1);
        argmin_kernel<<<ARGMIN_GRID, 128>>>(nullptr, nullptr, nullptr, nullptr,
                                            nullptr, 1);
        residual_kernel<<<RES_GRID, 256>>>(nullptr, nullptr, nullptr, nullptr, 1);
        init3_kernel<<<1, 32>>>(nullptr, 1);
        final_kernel<<<FINAL_GRID, 256>>>(nullptr, nullptr, nullptr, nullptr,
                                          nullptr, 1);
        scalars_kernel<<<1, 32>>>(nullptr, 1);
        cudaDeviceSynchronize();

        cudaMemGetInfo(&f1, &tot);
        fprintf(stderr, "[eager] free before=%zu after=%zu delta=%lld\n",
                f0, f1, (long long)f0 - (long long)f1);
    }
};
static ModuleEagerLoad s_eager_load;
}  // namespace

// ---------------------------------------------------------------------------
extern "C" void kernel_launch(void* const* d_in, const int* in_sizes, int n_in,
                              void* d_out, int out_size)
{
    const float* inputs    = (const float*)d_in[0];
    const float* embedding = (const float*)d_in[1];

    float* out     = (float*)d_out;
    float* out_q   = out;                            // N*D: residual scratch, then quantized_sum
    float* out_idx = out + (size_t)NTOK * DIM;       // L*N indices (as f32)
    float* out3    = out_idx + (size_t)NLVL * NTOK;  // vq, codebook, commit

    float* en2_base = nullptr;
    uint32_t* emb16_base = nullptr;
    cudaGetSymbolAddress((void**)&en2_base, g_en2);
    cudaGetSymbolAddress((void**)&emb16_base, g_emb16);

    init3_kernel<<<1, 32>>>(out3, 0);
    prep_kernel<<<PREP_GRID, 256>>>(embedding, 0);
    for (int lvl = 0; lvl < NLVL; lvl++) {
        const float* emb_l = embedding + (size_t)lvl * NCODE * DIM;
        const float* src   = (lvl == 0) ? inputs : out_q;
        argmin_kernel<<<ARGMIN_GRID, 128>>>(
            src, emb_l, emb16_base + (size_t)lvl * NCODE * 64,
            en2_base + (size_t)lvl * NCODE,
            out_idx + (size_t)lvl * NTOK, 0);
        if (lvl < NLVL - 1)
            residual_kernel<<<RES_GRID, 256>>>(
                src, emb_l, out_idx + (size_t)lvl * NTOK, out_q, 0);
    }
    final_kernel<<<FINAL_GRID, 256>>>(inputs, embedding, out_idx, out_q, out3, 0);
    scalars_kernel<<<1, 32>>>(out3, 0);
}